// round 12
// baseline (speedup 1.0000x reference)
#include <cuda_runtime.h>
#include <cstddef>

#define BATCH 16
#define NPTS  1024
#define DIM   64
#define L2E_EPS 144.2695040888963f   // log2(e)/eps
#define LOG2_A  (-9.999985227f)      // log2(1/1024 + 1e-8)
#define CPB   37
#define GRID  (BATCH * CPB)
#define ITERS 100
#define ROW_TINY 9.094947e-13f       // 2^-40
#define COL_TINY 9.5367432e-7f       // 2^-20
#define BOOST 80.0f
#define NCACHE_H 6                   // cached rows per half (12 total = 48KB)
#define SMEM_DYN (12 * 1024 * 4)

__device__ float    g_C[BATCH * NPTS * NPTS];
__device__ float    g_uL[BATCH * NPTS];
__device__ float    g_vL[BATCH * NPTS];
__device__ float    g_xn[BATCH * NPTS];
__device__ float    g_yn[BATCH * NPTS];
__device__ unsigned g_bar[BATCH];
__device__ float    g_cpart[BATCH * CPB * NPTS];
__device__ float    g_part[GRID];

__device__ __forceinline__ float ex2f(float x) {
    float y; asm("ex2.approx.ftz.f32 %0, %1;" : "=f"(y) : "f"(x)); return y;
}
__device__ __forceinline__ float lg2f(float x) {
    float y; asm("lg2.approx.f32 %0, %1;" : "=f"(y) : "f"(x)); return y;
}
__device__ __forceinline__ void lse_acc(float& m, float& s, float w) {
    float d = w - m, mn = fmaxf(m, w);
    float t = ex2f(0.0f - fabsf(d));
    float a = (d > 0.0f) ? t : 1.0f;
    float b = (d > 0.0f) ? 1.0f : t;
    s = fmaf(s, a, b); m = mn;
}
__device__ __forceinline__ void lse_merge(float& m, float& s, float m2, float s2) {
    float M = fmaxf(m, m2);
    s = fmaf(s, ex2f(m - M), s2 * ex2f(m2 - M));
    m = M;
}
__device__ __forceinline__ void batch_barrier(int b, unsigned target) {
    __syncthreads();
    if (threadIdx.x == 0) {
        unsigned old;
        asm volatile("atom.release.gpu.global.add.u32 %0, [%1], 1;"
                     : "=r"(old) : "l"(&g_bar[b]) : "memory");
        unsigned cur;
        do {
            asm volatile("ld.acquire.gpu.global.u32 %0, [%1];"
                         : "=r"(cur) : "l"(&g_bar[b]) : "memory");
            if (cur >= target) break;
            __nanosleep(20);
        } while (true);
    }
    __syncthreads();
}
__device__ __forceinline__ void half_bar(int half) {
    asm volatile("bar.sync %0, %1;" :: "r"(1 + half), "r"(128) : "memory");
}

__global__ __launch_bounds__(256) void init_kernel(const float* __restrict__ x,
                                                   const float* __restrict__ y) {
    int tid = threadIdx.x, w = tid >> 5, lane = tid & 31;
    int r = blockIdx.x * 8 + w;
    bool is_x = (r < BATCH * NPTS);
    const float* src = is_x ? (x + (size_t)r * DIM)
                            : (y + (size_t)(r - BATCH * NPTS) * DIM);
    float a = src[lane], b = src[lane + 32];
    float sq = a * a + b * b;
    #pragma unroll
    for (int o = 16; o; o >>= 1) sq += __shfl_xor_sync(0xffffffffu, sq, o);
    if (lane == 0) { if (is_x) g_xn[r] = sq; else g_yn[r - BATCH * NPTS] = sq; }
    int g = blockIdx.x * 256 + tid;
    if (g < BATCH * NPTS) { g_vL[g] = 0.0f; g_uL[g] = 0.0f; }
    if (g < BATCH) g_bar[g] = 0u;
}

__global__ __launch_bounds__(256) void c_kernel(const float* __restrict__ x,
                                                const float* __restrict__ y) {
    __shared__ float xs[64][65];
    __shared__ float ys[64][65];
    int tid = threadIdx.x;
    int b = blockIdx.z, i0 = blockIdx.y * 64, j0 = blockIdx.x * 64;
    const float* xb = x + ((size_t)(b * NPTS + i0)) * DIM;
    const float* yb = y + ((size_t)(b * NPTS + j0)) * DIM;
    #pragma unroll
    for (int t = 0; t < 4; t++) {
        int e = tid + t * 256;
        int row = e >> 4, c4 = (e & 15) * 4;
        float4 vx = *(const float4*)(xb + row * DIM + c4);
        xs[row][c4] = vx.x; xs[row][c4+1] = vx.y; xs[row][c4+2] = vx.z; xs[row][c4+3] = vx.w;
        float4 vy = *(const float4*)(yb + row * DIM + c4);
        ys[row][c4] = vy.x; ys[row][c4+1] = vy.y; ys[row][c4+2] = vy.z; ys[row][c4+3] = vy.w;
    }
    __syncthreads();
    int tx = tid & 15, ty = tid >> 4;
    float acc[4][4];
    #pragma unroll
    for (int r = 0; r < 4; r++)
        #pragma unroll
        for (int c = 0; c < 4; c++) acc[r][c] = 0.0f;
    #pragma unroll 16
    for (int d = 0; d < 64; d++) {
        float a0 = xs[ty*4+0][d], a1 = xs[ty*4+1][d], a2 = xs[ty*4+2][d], a3 = xs[ty*4+3][d];
        float b0 = ys[tx*4+0][d], b1 = ys[tx*4+1][d], b2 = ys[tx*4+2][d], b3 = ys[tx*4+3][d];
        acc[0][0]=fmaf(a0,b0,acc[0][0]); acc[0][1]=fmaf(a0,b1,acc[0][1]);
        acc[0][2]=fmaf(a0,b2,acc[0][2]); acc[0][3]=fmaf(a0,b3,acc[0][3]);
        acc[1][0]=fmaf(a1,b0,acc[1][0]); acc[1][1]=fmaf(a1,b1,acc[1][1]);
        acc[1][2]=fmaf(a1,b2,acc[1][2]); acc[1][3]=fmaf(a1,b3,acc[1][3]);
        acc[2][0]=fmaf(a2,b0,acc[2][0]); acc[2][1]=fmaf(a2,b1,acc[2][1]);
        acc[2][2]=fmaf(a2,b2,acc[2][2]); acc[2][3]=fmaf(a2,b3,acc[2][3]);
        acc[3][0]=fmaf(a3,b0,acc[3][0]); acc[3][1]=fmaf(a3,b1,acc[3][1]);
        acc[3][2]=fmaf(a3,b2,acc[3][2]); acc[3][3]=fmaf(a3,b3,acc[3][3]);
    }
    float* Cb = g_C + ((size_t)b << 20);
    float yn0 = g_yn[b*NPTS + j0 + tx*4 + 0];
    float yn1 = g_yn[b*NPTS + j0 + tx*4 + 1];
    float yn2 = g_yn[b*NPTS + j0 + tx*4 + 2];
    float yn3 = g_yn[b*NPTS + j0 + tx*4 + 3];
    #pragma unroll
    for (int r = 0; r < 4; r++) {
        int i = i0 + ty * 4 + r;
        float xni = g_xn[b*NPTS + i];
        float4 o;
        o.x = xni + yn0 - 2.0f*acc[r][0];
        o.y = xni + yn1 - 2.0f*acc[r][1];
        o.z = xni + yn2 - 2.0f*acc[r][2];
        o.w = xni + yn3 - 2.0f*acc[r][3];
        *(float4*)(Cb + (size_t)i * NPTS + j0 + tx*4) = o;
    }
}

// persistent fused Sinkhorn: one pass over C per iteration, 12 rows of C
// cached in SMEM per CTA for all 100 iterations.
__global__ __launch_bounds__(256, 4) void sink_kernel(float* __restrict__ out) {
    extern __shared__ float sh_C[];          // [12][1024]: 6 per half
    __shared__ float sh_buf[1024];
    __shared__ float sh_uold[32];
    __shared__ float sh_r1[2][2][4];
    __shared__ float sh_r2[2][2][4];
    __shared__ int   sh_flag;
    int tid = threadIdx.x, w = tid >> 5, lane = tid & 31;
    int half = w >> 2, wg = w & 3;
    int b = blockIdx.x / CPB, idx = blockIdx.x - b * CPB;
    int r0 = (idx * NPTS) / CPB, r1 = ((idx + 1) * NPTS) / CPB, cnt = r1 - r0;
    int myr0 = r0 + (half ? 14 : 0);
    int mycnt = half ? cnt - 14 : 14;
    const float* Cb = g_C + ((size_t)b << 20);
    float* uLb = g_uL + (b << 10);
    float* vLb = g_vL + (b << 10);
    float* cpart = g_cpart + (size_t)(b * CPB) * NPTS;
    int cb = wg * 256 + lane * 4;      // lane's 8 cols: cb..+3, cb+128..+131
    unsigned nbar = 0;

    // ---- one-time: cache rows (local 0..5 and 14..19) into SMEM ----
    #pragma unroll 1
    for (int q = tid; q < 12 * 256; q += 256) {
        int row = q >> 8;                        // 0..11 (256 float4 per row)
        int f4  = q & 255;
        int grow = r0 + (row < 6 ? row : row + 8);
        *(float4*)(sh_C + row * 1024 + f4 * 4) =
            *(const float4*)(Cb + ((size_t)grow << 10) + f4 * 4);
    }
    __syncthreads();

    for (int it = 0; it < ITERS; ++it) {
        float vLc[8];
        *(float4*)vLc     = *(const float4*)(vLb + cb);
        *(float4*)(vLc+4) = *(const float4*)(vLb + cb + 128);
        float cs[8] = {0,0,0,0,0,0,0,0};
        if (tid < cnt) sh_uold[tid] = uLb[r0 + tid];
        if (tid == 0) sh_flag = 0;
        __syncthreads();

        // ---- phase A: rows + fused gauge-linear col accumulation ----
        #pragma unroll 1
        for (int t = 0; t < mycnt; t++) {
            int r = myr0 + t, par = t & 1;
            float uold = sh_uold[r - r0];
            float ofr = uold - LOG2_A;
            float4 c0, c1;
            if (t < NCACHE_H) {
                const float* Cs = sh_C + (half * 6 + t) * 1024 + cb;
                c0 = *(const float4*)Cs;
                c1 = *(const float4*)(Cs + 128);
            } else {
                const float* Cr = Cb + ((size_t)r << 10) + cb;
                c0 = *(const float4*)Cr;
                c1 = *(const float4*)(Cr + 128);
            }
            float e[8], tv[8];
            e[0]=fmaf(c0.x,-L2E_EPS,vLc[0]+ofr); e[1]=fmaf(c0.y,-L2E_EPS,vLc[1]+ofr);
            e[2]=fmaf(c0.z,-L2E_EPS,vLc[2]+ofr); e[3]=fmaf(c0.w,-L2E_EPS,vLc[3]+ofr);
            e[4]=fmaf(c1.x,-L2E_EPS,vLc[4]+ofr); e[5]=fmaf(c1.y,-L2E_EPS,vLc[5]+ofr);
            e[6]=fmaf(c1.z,-L2E_EPS,vLc[6]+ofr); e[7]=fmaf(c1.w,-L2E_EPS,vLc[7]+ofr);
            #pragma unroll
            for (int k = 0; k < 8; k++) tv[k] = ex2f(e[k]);   // e <= 0 guaranteed
            float s8 = ((tv[0]+tv[1])+(tv[2]+tv[3]))+((tv[4]+tv[5])+(tv[6]+tv[7]));
            #pragma unroll
            for (int o = 16; o; o >>= 1) s8 += __shfl_xor_sync(0xffffffffu, s8, o);
            if (lane == 0) sh_r1[half][par][wg] = s8;
            half_bar(half);
            float srow = (sh_r1[half][par][0]+sh_r1[half][par][1])
                       + (sh_r1[half][par][2]+sh_r1[half][par][3]);
            float Mrow = 0.0f;
            if (srow < ROW_TINY) {      // exact fallback (early iterations)
                float me = fmaxf(fmaxf(fmaxf(e[0],e[1]),fmaxf(e[2],e[3])),
                                 fmaxf(fmaxf(e[4],e[5]),fmaxf(e[6],e[7])));
                #pragma unroll
                for (int o = 16; o; o >>= 1) me = fmaxf(me, __shfl_xor_sync(0xffffffffu, me, o));
                if (lane == 0) sh_r2[half][0][wg] = me;
                half_bar(half);
                Mrow = fmaxf(fmaxf(sh_r2[half][0][0],sh_r2[half][0][1]),
                             fmaxf(sh_r2[half][0][2],sh_r2[half][0][3]));
                #pragma unroll
                for (int k = 0; k < 8; k++) tv[k] = ex2f(e[k] - Mrow);
                float z = ((tv[0]+tv[1])+(tv[2]+tv[3]))+((tv[4]+tv[5])+(tv[6]+tv[7]));
                #pragma unroll
                for (int o = 16; o; o >>= 1) z += __shfl_xor_sync(0xffffffffu, z, o);
                if (lane == 0) sh_r2[half][1][wg] = z;
                half_bar(half);
                srow = (sh_r2[half][1][0]+sh_r2[half][1][1])
                     + (sh_r2[half][1][2]+sh_r2[half][1][3]);
            }
            float l2s = lg2f(srow);
            if (wg == 0 && lane == 0) uLb[r] = uold - (Mrow + l2s);
            float pd = ex2f(BOOST - l2s);           // col terms: tv * pd
            #pragma unroll
            for (int k = 0; k < 8; k++) cs[k] = fmaf(tv[k], pd, cs[k]);
        }
        // merge halves (plain adds), store CTA partial per column
        __syncthreads();
        if (half == 1) {
            #pragma unroll
            for (int k = 0; k < 8; k++) sh_buf[(wg*32+lane)*8 + k] = cs[k];
        }
        __syncthreads();
        if (half == 0) {
            #pragma unroll
            for (int k = 0; k < 8; k++) {
                int col = cb + (k & 4) * 32 + (k & 3);
                cpart[(size_t)idx * NPTS + col] = cs[k] + sh_buf[(wg*32+lane)*8 + k];
            }
        }
        batch_barrier(b, (unsigned)CPB * (++nbar));

        // ---- phase B: sum 37 partials per owned column -> v ----
        {
            int cidx = tid >> 3, sub = tid & 7;
            int c = r0 + (cidx < cnt ? cidx : cnt - 1);
            float s = 0.0f;
            for (int kk = sub; kk < CPB; kk += 8)
                s += cpart[(size_t)kk * NPTS + c];
            s += __shfl_xor_sync(0xffffffffu, s, 1);
            s += __shfl_xor_sync(0xffffffffu, s, 2);
            s += __shfl_xor_sync(0xffffffffu, s, 4);
            if (sub == 0 && cidx < cnt) {
                if (s >= COL_TINY) vLb[c] = vLb[c] - (lg2f(s) - BOOST);
                else sh_flag = 1;
            }
        }
        __syncthreads();
        if (sh_flag) {   // exact strided col pass for this CTA's columns
            int cc = r0 + (lane < cnt ? lane : cnt - 1);
            const float* Cp = Cb + (((size_t)w * 128) << 10) + cc;
            const float* up = uLb + w * 128;
            float m = -1e30f, s = 0.0f;
            #pragma unroll 4
            for (int r = 0; r < 128; r++) {
                float wv = fmaf(__ldg(Cp + ((size_t)r << 10)), -L2E_EPS, __ldg(up + r));
                lse_acc(m, s, wv);
            }
            sh_buf[tid] = m; sh_buf[256 + tid] = s;
            __syncthreads();
            if (w == 0) {
                float M = sh_buf[lane], S = sh_buf[256 + lane];
                #pragma unroll
                for (int gg = 1; gg < 8; gg++)
                    lse_merge(M, S, sh_buf[gg*32+lane], sh_buf[256+gg*32+lane]);
                if (lane < cnt) vLb[r0 + lane] = LOG2_A - (M + lg2f(S));
            }
            __syncthreads();
        }
        batch_barrier(b, (unsigned)CPB * (++nbar));
    }

    // ---- cost: out[b] = sum_ij 2^(uL+vL-C*L2E) * C ----
    #pragma unroll
    for (int t = 0; t < 4; t++) sh_buf[tid + t*256] = vLb[tid + t*256];
    __syncthreads();
    float acc = 0.0f;
    #pragma unroll 1
    for (int r = r0 + w; r < r1; r += 8) {
        float uL = uLb[r];
        int local = r - r0;
        int ci = (local < 6) ? local : ((local >= 14 && local < 20) ? local - 8 : -1);
        const float* Crow = (ci >= 0) ? (sh_C + ci * 1024)
                                      : (Cb + ((size_t)r << 10));
        #pragma unroll
        for (int q = 0; q < 8; q++) {
            int j = q * 128 + lane * 4;
            float4 c  = *(const float4*)(Crow + j);
            float4 vl = *(const float4*)(sh_buf + j);
            float p;
            p = ex2f(fmaf(c.x, -L2E_EPS, uL + vl.x)); acc = fmaf(p, c.x, acc);
            p = ex2f(fmaf(c.y, -L2E_EPS, uL + vl.y)); acc = fmaf(p, c.y, acc);
            p = ex2f(fmaf(c.z, -L2E_EPS, uL + vl.z)); acc = fmaf(p, c.z, acc);
            p = ex2f(fmaf(c.w, -L2E_EPS, uL + vl.w)); acc = fmaf(p, c.w, acc);
        }
    }
    #pragma unroll
    for (int o = 16; o; o >>= 1) acc += __shfl_xor_sync(0xffffffffu, acc, o);
    if (lane == 0) ((float*)sh_r1)[w] = acc;
    __syncthreads();
    if (tid == 0) {
        float t = 0.0f;
        #pragma unroll
        for (int i = 0; i < 8; i++) t += ((float*)sh_r1)[i];
        g_part[blockIdx.x] = t;
    }
    batch_barrier(b, (unsigned)CPB * (++nbar));
    if (idx == 0 && tid == 0) {
        float t = 0.0f;
        for (int k = 0; k < CPB; k++) t += g_part[b * CPB + k];
        out[b] = t;
    }
}

extern "C" void kernel_launch(void* const* d_in, const int* in_sizes, int n_in,
                              void* d_out, int out_size) {
    (void)in_sizes; (void)n_in; (void)out_size;
    const float* x = (const float*)d_in[0];
    const float* y = (const float*)d_in[1];
    float* out = (float*)d_out;

    cudaFuncSetAttribute(sink_kernel, cudaFuncAttributeMaxDynamicSharedMemorySize, SMEM_DYN);
    init_kernel<<<4096, 256>>>(x, y);
    c_kernel<<<dim3(16, 16, 16), 256>>>(x, y);
    sink_kernel<<<GRID, 256, SMEM_DYN>>>(out);
}

// round 13
// speedup vs baseline: 1.0951x; 1.0951x over previous
#include <cuda_runtime.h>
#include <cstddef>

#define BATCH 16
#define NPTS  1024
#define DIM   64
#define L2E_EPS 144.2695040888963f   // log2(e)/eps
#define LOG2_A  (-9.999985227f)      // log2(1/1024 + 1e-8)
#define CPB   37
#define GRID  (BATCH * CPB)
#define ITERS 100
#define ROW_TINY 9.094947e-13f       // 2^-40
#define COL_TINY 9.5367432e-7f       // 2^-20
#define BOOST 80.0f

__device__ float    g_C[BATCH * NPTS * NPTS];
__device__ float    g_uL[BATCH * NPTS];
__device__ float    g_vL[BATCH * NPTS];
__device__ float    g_xn[BATCH * NPTS];
__device__ float    g_yn[BATCH * NPTS];
__device__ unsigned g_bar[BATCH];
__device__ float    g_cpart[BATCH * CPB * NPTS];
__device__ float    g_part[GRID];

__device__ __forceinline__ float ex2f(float x) {
    float y; asm("ex2.approx.ftz.f32 %0, %1;" : "=f"(y) : "f"(x)); return y;
}
__device__ __forceinline__ float lg2f(float x) {
    float y; asm("lg2.approx.f32 %0, %1;" : "=f"(y) : "f"(x)); return y;
}
__device__ __forceinline__ void lse_acc(float& m, float& s, float w) {
    float d = w - m, mn = fmaxf(m, w);
    float t = ex2f(0.0f - fabsf(d));
    float a = (d > 0.0f) ? t : 1.0f;
    float b = (d > 0.0f) ? 1.0f : t;
    s = fmaf(s, a, b); m = mn;
}
__device__ __forceinline__ void lse_merge(float& m, float& s, float m2, float s2) {
    float M = fmaxf(m, m2);
    s = fmaf(s, ex2f(m - M), s2 * ex2f(m2 - M));
    m = M;
}
__device__ __forceinline__ void batch_barrier(int b, unsigned target) {
    __syncthreads();
    if (threadIdx.x == 0) {
        unsigned old;
        asm volatile("atom.release.gpu.global.add.u32 %0, [%1], 1;"
                     : "=r"(old) : "l"(&g_bar[b]) : "memory");
        unsigned cur;
        do {
            asm volatile("ld.acquire.gpu.global.u32 %0, [%1];"
                         : "=r"(cur) : "l"(&g_bar[b]) : "memory");
            if (cur >= target) break;
            __nanosleep(20);
        } while (true);
    }
    __syncthreads();
}
__device__ __forceinline__ void half_bar(int half) {
    asm volatile("bar.sync %0, %1;" :: "r"(1 + half), "r"(128) : "memory");
}

__global__ __launch_bounds__(256) void init_kernel(const float* __restrict__ x,
                                                   const float* __restrict__ y) {
    int tid = threadIdx.x, w = tid >> 5, lane = tid & 31;
    int r = blockIdx.x * 8 + w;
    bool is_x = (r < BATCH * NPTS);
    const float* src = is_x ? (x + (size_t)r * DIM)
                            : (y + (size_t)(r - BATCH * NPTS) * DIM);
    float a = src[lane], b = src[lane + 32];
    float sq = a * a + b * b;
    #pragma unroll
    for (int o = 16; o; o >>= 1) sq += __shfl_xor_sync(0xffffffffu, sq, o);
    if (lane == 0) { if (is_x) g_xn[r] = sq; else g_yn[r - BATCH * NPTS] = sq; }
    int g = blockIdx.x * 256 + tid;
    if (g < BATCH * NPTS) { g_vL[g] = 0.0f; g_uL[g] = 0.0f; }
    if (g < BATCH) g_bar[g] = 0u;
}

__global__ __launch_bounds__(256) void c_kernel(const float* __restrict__ x,
                                                const float* __restrict__ y) {
    __shared__ float xs[64][65];
    __shared__ float ys[64][65];
    int tid = threadIdx.x;
    int b = blockIdx.z, i0 = blockIdx.y * 64, j0 = blockIdx.x * 64;
    const float* xb = x + ((size_t)(b * NPTS + i0)) * DIM;
    const float* yb = y + ((size_t)(b * NPTS + j0)) * DIM;
    #pragma unroll
    for (int t = 0; t < 4; t++) {
        int e = tid + t * 256;
        int row = e >> 4, c4 = (e & 15) * 4;
        float4 vx = *(const float4*)(xb + row * DIM + c4);
        xs[row][c4] = vx.x; xs[row][c4+1] = vx.y; xs[row][c4+2] = vx.z; xs[row][c4+3] = vx.w;
        float4 vy = *(const float4*)(yb + row * DIM + c4);
        ys[row][c4] = vy.x; ys[row][c4+1] = vy.y; ys[row][c4+2] = vy.z; ys[row][c4+3] = vy.w;
    }
    __syncthreads();
    int tx = tid & 15, ty = tid >> 4;
    float acc[4][4];
    #pragma unroll
    for (int r = 0; r < 4; r++)
        #pragma unroll
        for (int c = 0; c < 4; c++) acc[r][c] = 0.0f;
    #pragma unroll 16
    for (int d = 0; d < 64; d++) {
        float a0 = xs[ty*4+0][d], a1 = xs[ty*4+1][d], a2 = xs[ty*4+2][d], a3 = xs[ty*4+3][d];
        float b0 = ys[tx*4+0][d], b1 = ys[tx*4+1][d], b2 = ys[tx*4+2][d], b3 = ys[tx*4+3][d];
        acc[0][0]=fmaf(a0,b0,acc[0][0]); acc[0][1]=fmaf(a0,b1,acc[0][1]);
        acc[0][2]=fmaf(a0,b2,acc[0][2]); acc[0][3]=fmaf(a0,b3,acc[0][3]);
        acc[1][0]=fmaf(a1,b0,acc[1][0]); acc[1][1]=fmaf(a1,b1,acc[1][1]);
        acc[1][2]=fmaf(a1,b2,acc[1][2]); acc[1][3]=fmaf(a1,b3,acc[1][3]);
        acc[2][0]=fmaf(a2,b0,acc[2][0]); acc[2][1]=fmaf(a2,b1,acc[2][1]);
        acc[2][2]=fmaf(a2,b2,acc[2][2]); acc[2][3]=fmaf(a2,b3,acc[2][3]);
        acc[3][0]=fmaf(a3,b0,acc[3][0]); acc[3][1]=fmaf(a3,b1,acc[3][1]);
        acc[3][2]=fmaf(a3,b2,acc[3][2]); acc[3][3]=fmaf(a3,b3,acc[3][3]);
    }
    float* Cb = g_C + ((size_t)b << 20);
    float yn0 = g_yn[b*NPTS + j0 + tx*4 + 0];
    float yn1 = g_yn[b*NPTS + j0 + tx*4 + 1];
    float yn2 = g_yn[b*NPTS + j0 + tx*4 + 2];
    float yn3 = g_yn[b*NPTS + j0 + tx*4 + 3];
    #pragma unroll
    for (int r = 0; r < 4; r++) {
        int i = i0 + ty * 4 + r;
        float xni = g_xn[b*NPTS + i];
        float4 o;
        o.x = xni + yn0 - 2.0f*acc[r][0];
        o.y = xni + yn1 - 2.0f*acc[r][1];
        o.z = xni + yn2 - 2.0f*acc[r][2];
        o.w = xni + yn3 - 2.0f*acc[r][3];
        *(float4*)(Cb + (size_t)i * NPTS + j0 + tx*4) = o;
    }
}

// persistent fused Sinkhorn: one pass over C per iteration, rows processed
// in pairs (one half-CTA barrier per pair, two reduction chains in flight).
__global__ __launch_bounds__(256, 4) void sink_kernel(float* __restrict__ out) {
    __shared__ float sh_buf[1024];
    __shared__ float sh_uold[32];
    __shared__ float sh_r1[2][2][4];
    __shared__ float sh_r2[2][2][4];
    __shared__ int   sh_flag;
    int tid = threadIdx.x, w = tid >> 5, lane = tid & 31;
    int half = w >> 2, wg = w & 3;
    int b = blockIdx.x / CPB, idx = blockIdx.x - b * CPB;
    int r0 = (idx * NPTS) / CPB, r1 = ((idx + 1) * NPTS) / CPB, cnt = r1 - r0;
    int myr0 = r0 + (half ? 14 : 0);
    int mycnt = half ? cnt - 14 : 14;           // 13 or 14
    const float* Cb = g_C + ((size_t)b << 20);
    float* uLb = g_uL + (b << 10);
    float* vLb = g_vL + (b << 10);
    float* cpart = g_cpart + (size_t)(b * CPB) * NPTS;
    int cb = wg * 256 + lane * 4;      // lane's 8 cols: cb..+3, cb+128..+131
    unsigned nbar = 0;

    for (int it = 0; it < ITERS; ++it) {
        float vLc[8];
        *(float4*)vLc     = *(const float4*)(vLb + cb);
        *(float4*)(vLc+4) = *(const float4*)(vLb + cb + 128);
        float cs[8] = {0,0,0,0,0,0,0,0};
        if (tid < cnt) sh_uold[tid] = uLb[r0 + tid];
        if (tid == 0) sh_flag = 0;
        __syncthreads();

        // ---- phase A: row pairs + fused gauge-linear col accumulation ----
        #pragma unroll 1
        for (int t = 0; t < 7; t++) {
            int rA = myr0 + 2 * t;
            bool validB = (2 * t + 1) < mycnt;
            float uoldA = sh_uold[rA - r0];
            float uoldB = sh_uold[validB ? (rA + 1 - r0) : (rA - r0)];
            float ofrA = uoldA - LOG2_A, ofrB = uoldB - LOG2_A;
            const float* CrA = Cb + ((size_t)rA << 10) + cb;
            const float* CrB = CrA + (validB ? 1024 : 0);
            float4 a0 = *(const float4*)CrA;
            float4 a1 = *(const float4*)(CrA + 128);
            float4 b0 = *(const float4*)CrB;
            float4 b1 = *(const float4*)(CrB + 128);
            float eA[8], eB[8], tvA[8], tvB[8];
            eA[0]=fmaf(a0.x,-L2E_EPS,vLc[0]+ofrA); eA[1]=fmaf(a0.y,-L2E_EPS,vLc[1]+ofrA);
            eA[2]=fmaf(a0.z,-L2E_EPS,vLc[2]+ofrA); eA[3]=fmaf(a0.w,-L2E_EPS,vLc[3]+ofrA);
            eA[4]=fmaf(a1.x,-L2E_EPS,vLc[4]+ofrA); eA[5]=fmaf(a1.y,-L2E_EPS,vLc[5]+ofrA);
            eA[6]=fmaf(a1.z,-L2E_EPS,vLc[6]+ofrA); eA[7]=fmaf(a1.w,-L2E_EPS,vLc[7]+ofrA);
            eB[0]=fmaf(b0.x,-L2E_EPS,vLc[0]+ofrB); eB[1]=fmaf(b0.y,-L2E_EPS,vLc[1]+ofrB);
            eB[2]=fmaf(b0.z,-L2E_EPS,vLc[2]+ofrB); eB[3]=fmaf(b0.w,-L2E_EPS,vLc[3]+ofrB);
            eB[4]=fmaf(b1.x,-L2E_EPS,vLc[4]+ofrB); eB[5]=fmaf(b1.y,-L2E_EPS,vLc[5]+ofrB);
            eB[6]=fmaf(b1.z,-L2E_EPS,vLc[6]+ofrB); eB[7]=fmaf(b1.w,-L2E_EPS,vLc[7]+ofrB);
            #pragma unroll
            for (int k = 0; k < 8; k++) { tvA[k] = ex2f(eA[k]); tvB[k] = ex2f(eB[k]); }
            float sA = ((tvA[0]+tvA[1])+(tvA[2]+tvA[3]))+((tvA[4]+tvA[5])+(tvA[6]+tvA[7]));
            float sB = ((tvB[0]+tvB[1])+(tvB[2]+tvB[3]))+((tvB[4]+tvB[5])+(tvB[6]+tvB[7]));
            #pragma unroll
            for (int o = 16; o; o >>= 1) {
                sA += __shfl_xor_sync(0xffffffffu, sA, o);
                sB += __shfl_xor_sync(0xffffffffu, sB, o);
            }
            if (lane == 0) { sh_r1[half][0][wg] = sA; sh_r1[half][1][wg] = sB; }
            half_bar(half);
            float srowA = (sh_r1[half][0][0]+sh_r1[half][0][1])
                        + (sh_r1[half][0][2]+sh_r1[half][0][3]);
            float srowB = (sh_r1[half][1][0]+sh_r1[half][1][1])
                        + (sh_r1[half][1][2]+sh_r1[half][1][3]);
            float MrowA = 0.0f, MrowB = 0.0f;
            if (srowA < ROW_TINY || srowB < ROW_TINY) {   // exact fallback (early only)
                float meA = fmaxf(fmaxf(fmaxf(eA[0],eA[1]),fmaxf(eA[2],eA[3])),
                                  fmaxf(fmaxf(eA[4],eA[5]),fmaxf(eA[6],eA[7])));
                float meB = fmaxf(fmaxf(fmaxf(eB[0],eB[1]),fmaxf(eB[2],eB[3])),
                                  fmaxf(fmaxf(eB[4],eB[5]),fmaxf(eB[6],eB[7])));
                #pragma unroll
                for (int o = 16; o; o >>= 1) {
                    meA = fmaxf(meA, __shfl_xor_sync(0xffffffffu, meA, o));
                    meB = fmaxf(meB, __shfl_xor_sync(0xffffffffu, meB, o));
                }
                if (lane == 0) { sh_r2[half][0][wg] = meA; sh_r2[half][1][wg] = meB; }
                half_bar(half);
                MrowA = fmaxf(fmaxf(sh_r2[half][0][0],sh_r2[half][0][1]),
                              fmaxf(sh_r2[half][0][2],sh_r2[half][0][3]));
                MrowB = fmaxf(fmaxf(sh_r2[half][1][0],sh_r2[half][1][1]),
                              fmaxf(sh_r2[half][1][2],sh_r2[half][1][3]));
                float zA = 0.0f, zB = 0.0f;
                #pragma unroll
                for (int k = 0; k < 8; k++) {
                    tvA[k] = ex2f(eA[k] - MrowA); zA += tvA[k];
                    tvB[k] = ex2f(eB[k] - MrowB); zB += tvB[k];
                }
                #pragma unroll
                for (int o = 16; o; o >>= 1) {
                    zA += __shfl_xor_sync(0xffffffffu, zA, o);
                    zB += __shfl_xor_sync(0xffffffffu, zB, o);
                }
                if (lane == 0) { sh_r2[half][0][wg] = zA; sh_r2[half][1][wg] = zB; }
                half_bar(half);
                srowA = (sh_r2[half][0][0]+sh_r2[half][0][1])
                      + (sh_r2[half][0][2]+sh_r2[half][0][3]);
                srowB = (sh_r2[half][1][0]+sh_r2[half][1][1])
                      + (sh_r2[half][1][2]+sh_r2[half][1][3]);
            }
            float l2sA = lg2f(srowA), l2sB = lg2f(srowB);
            if (wg == 0 && lane == 0) {
                uLb[rA] = uoldA - (MrowA + l2sA);
                if (validB) uLb[rA + 1] = uoldB - (MrowB + l2sB);
            }
            float pdA = ex2f(BOOST - l2sA);
            float pdB = validB ? ex2f(BOOST - l2sB) : 0.0f;
            #pragma unroll
            for (int k = 0; k < 8; k++)
                cs[k] = fmaf(tvA[k], pdA, fmaf(tvB[k], pdB, cs[k]));
        }
        // merge halves (plain adds), store CTA partial per column
        __syncthreads();
        if (half == 1) {
            #pragma unroll
            for (int k = 0; k < 8; k++) sh_buf[(wg*32+lane)*8 + k] = cs[k];
        }
        __syncthreads();
        if (half == 0) {
            #pragma unroll
            for (int k = 0; k < 8; k++) {
                int col = cb + (k & 4) * 32 + (k & 3);
                cpart[(size_t)idx * NPTS + col] = cs[k] + sh_buf[(wg*32+lane)*8 + k];
            }
        }
        batch_barrier(b, (unsigned)CPB * (++nbar));

        // ---- phase B: sum 37 partials per owned column -> v ----
        {
            int cidx = tid >> 3, sub = tid & 7;
            int c = r0 + (cidx < cnt ? cidx : cnt - 1);
            float s = 0.0f;
            #pragma unroll
            for (int kk = 0; kk < 5; kk++) {
                int p = sub + kk * 8;
                if (p < CPB) s += cpart[(size_t)p * NPTS + c];
            }
            s += __shfl_xor_sync(0xffffffffu, s, 1);
            s += __shfl_xor_sync(0xffffffffu, s, 2);
            s += __shfl_xor_sync(0xffffffffu, s, 4);
            if (sub == 0 && cidx < cnt) {
                if (s >= COL_TINY) vLb[c] = vLb[c] - (lg2f(s) - BOOST);
                else sh_flag = 1;
            }
        }
        __syncthreads();
        if (sh_flag) {   // exact strided col pass for this CTA's columns
            int cc = r0 + (lane < cnt ? lane : cnt - 1);
            const float* Cp = Cb + (((size_t)w * 128) << 10) + cc;
            const float* up = uLb + w * 128;
            float m = -1e30f, s = 0.0f;
            #pragma unroll 4
            for (int r = 0; r < 128; r++) {
                float wv = fmaf(__ldg(Cp + ((size_t)r << 10)), -L2E_EPS, __ldg(up + r));
                lse_acc(m, s, wv);
            }
            sh_buf[tid] = m; sh_buf[256 + tid] = s;
            __syncthreads();
            if (w == 0) {
                float M = sh_buf[lane], S = sh_buf[256 + lane];
                #pragma unroll
                for (int gg = 1; gg < 8; gg++)
                    lse_merge(M, S, sh_buf[gg*32+lane], sh_buf[256+gg*32+lane]);
                if (lane < cnt) vLb[r0 + lane] = LOG2_A - (M + lg2f(S));
            }
            __syncthreads();
        }
        batch_barrier(b, (unsigned)CPB * (++nbar));
    }

    // ---- cost: out[b] = sum_ij 2^(uL+vL-C*L2E) * C ----
    #pragma unroll
    for (int t = 0; t < 4; t++) sh_buf[tid + t*256] = vLb[tid + t*256];
    __syncthreads();
    float acc = 0.0f;
    #pragma unroll 1
    for (int r = r0 + w; r < r1; r += 8) {
        float uL = uLb[r];
        const float* Crow = Cb + ((size_t)r << 10);
        #pragma unroll
        for (int q = 0; q < 8; q++) {
            int j = q * 128 + lane * 4;
            float4 c  = *(const float4*)(Crow + j);
            float4 vl = *(const float4*)(sh_buf + j);
            float p;
            p = ex2f(fmaf(c.x, -L2E_EPS, uL + vl.x)); acc = fmaf(p, c.x, acc);
            p = ex2f(fmaf(c.y, -L2E_EPS, uL + vl.y)); acc = fmaf(p, c.y, acc);
            p = ex2f(fmaf(c.z, -L2E_EPS, uL + vl.z)); acc = fmaf(p, c.z, acc);
            p = ex2f(fmaf(c.w, -L2E_EPS, uL + vl.w)); acc = fmaf(p, c.w, acc);
        }
    }
    #pragma unroll
    for (int o = 16; o; o >>= 1) acc += __shfl_xor_sync(0xffffffffu, acc, o);
    if (lane == 0) ((float*)sh_r1)[w] = acc;
    __syncthreads();
    if (tid == 0) {
        float t = 0.0f;
        #pragma unroll
        for (int i = 0; i < 8; i++) t += ((float*)sh_r1)[i];
        g_part[blockIdx.x] = t;
    }
    batch_barrier(b, (unsigned)CPB * (++nbar));
    if (idx == 0 && tid == 0) {
        float t = 0.0f;
        for (int k = 0; k < CPB; k++) t += g_part[b * CPB + k];
        out[b] = t;
    }
}

extern "C" void kernel_launch(void* const* d_in, const int* in_sizes, int n_in,
                              void* d_out, int out_size) {
    (void)in_sizes; (void)n_in; (void)out_size;
    const float* x = (const float*)d_in[0];
    const float* y = (const float*)d_in[1];
    float* out = (float*)d_out;

    init_kernel<<<4096, 256>>>(x, y);
    c_kernel<<<dim3(16, 16, 16), 256>>>(x, y);
    sink_kernel<<<GRID, 256>>>(out);
}